// round 1
// baseline (speedup 1.0000x reference)
#include <cuda_runtime.h>

// Problem constants (fixed by the reference): x [8,1024,512] fp32, codebook [8192,512] fp32.
#define DIMV      512
#define KCB       8192
#define BM        64
#define BN        64
#define BK        32
#define NTILES_N  (KCB / BN)     // 128
#define NTILES_K  (DIMV / BK)    // 16
#define TOTAL_T   (NTILES_N * NTILES_K)
#define ROW_F4    (DIMV / 4)     // 128 float4 per row

__device__ float g_esq[KCB];

// ---------------------------------------------------------------------------
// e_sq precompute: one warp per codebook row.
// ---------------------------------------------------------------------------
__global__ void esq_kernel(const float4* __restrict__ e4) {
    int row  = blockIdx.x * 8 + (threadIdx.x >> 5);
    int lane = threadIdx.x & 31;
    const float4* p = e4 + (size_t)row * ROW_F4;
    float s = 0.f;
#pragma unroll
    for (int c = 0; c < 4; ++c) {
        float4 v = p[lane + 32 * c];
        s += v.x * v.x + v.y * v.y + v.z * v.z + v.w * v.w;
    }
#pragma unroll
    for (int off = 16; off; off >>= 1)
        s += __shfl_down_sync(0xFFFFFFFFu, s, off);
    if (lane == 0) g_esq[row] = s;
}

// ---------------------------------------------------------------------------
// Swizzled transposed smem store: logical (k, m) -> float index
//   k*64 + (((m>>2) ^ (k>>2)) << 2) + (m&3)
// Conflict-free scalar stores; vectorized (float4) conflict-minimal reads.
// ---------------------------------------------------------------------------
__device__ __forceinline__ void storeT(float* S, float4 v, int f) {
    int r   = f >> 3;          // tile row (m), 0..63
    int qq  = f & 7;           // k-chunk, k = 4*qq + cc
    int col = (((r >> 2) ^ qq) << 2) | (r & 3);
    S[(4 * qq + 0) * BM + col] = v.x;
    S[(4 * qq + 1) * BM + col] = v.y;
    S[(4 * qq + 2) * BM + col] = v.z;
    S[(4 * qq + 3) * BM + col] = v.w;
}

// ---------------------------------------------------------------------------
// Fused GEMM (scores = 2*x.E^T - e_sq) + per-row argmax + codeword gather.
// Grid: nRows/64 blocks of 256 threads. Each block: 64 rows vs all 8192 codes.
// ---------------------------------------------------------------------------
__global__ __launch_bounds__(256, 1)
void vq_kernel(const float4* __restrict__ x4, const float4* __restrict__ e4,
               float* __restrict__ out, int writeIdx, int nRows) {
    __shared__ float As[2][BK * BM];
    __shared__ float Bs[2][BK * BN];
    __shared__ int   sBest[BM];

    const int tid = threadIdx.x;
    const int tx  = tid & 15;      // codeword-col group (4 cols)
    const int ty  = tid >> 4;      // row group (4 rows)
    const int rowBase = blockIdx.x * BM;

    float acc[4][4];
#pragma unroll
    for (int i = 0; i < 4; ++i)
#pragma unroll
        for (int j = 0; j < 4; ++j) acc[i][j] = 0.f;

    float bestV[4];
    int   bestI[4];
#pragma unroll
    for (int i = 0; i < 4; ++i) { bestV[i] = -3.4e38f; bestI[i] = 0; }

    float4 pa0, pa1, pb0, pb1;
    const int f0 = tid, f1 = tid + 256;
    const int r0 = f0 >> 3, q0 = f0 & 7;
    const int r1 = f1 >> 3, q1 = f1 & 7;

#define FETCH(T)                                                               \
    {                                                                          \
        int kt = (T) & 15, nt = (T) >> 4;                                      \
        int kc = kt * 8;                                                       \
        pa0 = x4[(size_t)(rowBase + r0) * ROW_F4 + kc + q0];                   \
        pa1 = x4[(size_t)(rowBase + r1) * ROW_F4 + kc + q1];                   \
        pb0 = e4[(size_t)(nt * BN + r0) * ROW_F4 + kc + q0];                   \
        pb1 = e4[(size_t)(nt * BN + r1) * ROW_F4 + kc + q1];                   \
    }
#define STORE(b)                                                               \
    {                                                                          \
        storeT(As[b], pa0, f0); storeT(As[b], pa1, f1);                        \
        storeT(Bs[b], pb0, f0); storeT(Bs[b], pb1, f1);                        \
    }

    FETCH(0);
    STORE(0);
    __syncthreads();

    int buf = 0;
    for (int T = 0; T < TOTAL_T; ++T) {
        const bool more = (T + 1 < TOTAL_T);
        if (more) FETCH(T + 1);

        const float4* A4 = (const float4*)As[buf];
        const float4* B4 = (const float4*)Bs[buf];
#pragma unroll
        for (int k = 0; k < BK; ++k) {
            const int q = k >> 2;
            float4 a = A4[k * 16 + (ty ^ q)];
            float4 b = B4[k * 16 + (tx ^ q)];
            float av[4] = {a.x, a.y, a.z, a.w};
            float bv[4] = {b.x, b.y, b.z, b.w};
#pragma unroll
            for (int i = 0; i < 4; ++i)
#pragma unroll
                for (int j = 0; j < 4; ++j)
                    acc[i][j] += av[i] * bv[j];
        }

        if ((T & 15) == 15) {           // finished K for this codeword tile
            const int nt = T >> 4;
            const int colBase = nt * BN + tx * 4;
#pragma unroll
            for (int j = 0; j < 4; ++j) {
                const float es = g_esq[colBase + j];
#pragma unroll
                for (int i = 0; i < 4; ++i) {
                    float s = 2.f * acc[i][j] - es;
                    if (s > bestV[i]) { bestV[i] = s; bestI[i] = colBase + j; }
                    acc[i][j] = 0.f;
                }
            }
        }

        if (more) STORE(buf ^ 1);
        __syncthreads();
        buf ^= 1;
    }
#undef FETCH
#undef STORE

    // Reduce argmax across the 16 tx-lanes sharing each row group (width-16).
#pragma unroll
    for (int off = 8; off; off >>= 1) {
#pragma unroll
        for (int i = 0; i < 4; ++i) {
            float ov = __shfl_down_sync(0xFFFFFFFFu, bestV[i], off, 16);
            int   oi = __shfl_down_sync(0xFFFFFFFFu, bestI[i], off, 16);
            if (ov > bestV[i] || (ov == bestV[i] && oi < bestI[i])) {
                bestV[i] = ov; bestI[i] = oi;
            }
        }
    }
    if (tx == 0) {
#pragma unroll
        for (int i = 0; i < 4; ++i) sBest[ty * 4 + i] = bestI[i];
    }
    __syncthreads();

    // Gather chosen codewords -> out[row*512 + :]
    float4* out4 = (float4*)out;
    const int wid = tid >> 5, lane = tid & 31;
    for (int r = wid; r < BM; r += 8) {
        const int idx = sBest[r];
        const float4* src = e4 + (size_t)idx * ROW_F4;
        float4* dst = out4 + (size_t)(rowBase + r) * ROW_F4;
#pragma unroll
        for (int c = 0; c < 4; ++c) dst[lane + 32 * c] = src[lane + 32 * c];
    }

    // Indices appended after the quantize block, cast to the fp32 out dtype.
    if (writeIdx && tid < BM) {
        out[(size_t)nRows * DIMV + rowBase + tid] = (float)sBest[tid];
    }
}

// ---------------------------------------------------------------------------
extern "C" void kernel_launch(void* const* d_in, const int* in_sizes, int n_in,
                              void* d_out, int out_size) {
    const float4* x4 = (const float4*)d_in[0];
    const float4* e4 = (const float4*)d_in[1];
    float* out = (float*)d_out;

    const int nRows = in_sizes[0] / DIMV;   // 8192
    const int kRows = in_sizes[1] / DIMV;   // 8192 codebook rows

    // e_sq: one warp per codebook row, 8 rows per 256-thread block.
    esq_kernel<<<kRows / 8, 256>>>(e4);

    const int writeIdx = (out_size >= nRows * DIMV + nRows) ? 1 : 0;
    vq_kernel<<<nRows / BM, 256>>>(x4, e4, out, writeIdx, nRows);
}

// round 3
// speedup vs baseline: 3.8831x; 3.8831x over previous
#include <cuda_runtime.h>
#include <cuda_fp16.h>
#include <cstdint>

// Problem constants: x [8192,512] fp32, codebook [8192,512] fp32.
#define DIMV    512
#define ROW_F4  128
#define KCB     8192
#define NROWSC  8192
#define BM      128
#define BN      128
#define KSTAGES 48          // effective fp16 K = 3*512 = 1536, 32 per stage
#define NBUF    4
#define SMEMSZ  (2*NBUF*8192 + 512)   // A(32KB) + B(32KB) + esq(512B)

// Preconverted fp16 split operands (static scratch — no runtime allocs).
__device__ __align__(16) __half g_xhi[NROWSC * DIMV];
__device__ __align__(16) __half g_xlo[NROWSC * DIMV];
__device__ __align__(16) __half g_ehi[KCB * DIMV];
__device__ __align__(16) __half g_elo[KCB * DIMV];
__device__ float g_esq[KCB];
__device__ unsigned long long g_best[NROWSC];

__device__ __forceinline__ uint32_t smem_u32(const void* p) {
    uint32_t a;
    asm("{ .reg .u64 t; cvta.to.shared.u64 t, %1; cvt.u32.u64 %0, t; }" : "=r"(a) : "l"(p));
    return a;
}
__device__ __forceinline__ void cpasync16(uint32_t dst, const void* src) {
    asm volatile("cp.async.cg.shared.global [%0], [%1], 16;"
                 :: "r"(dst), "l"(__cvta_generic_to_global(src)) : "memory");
}
__device__ __forceinline__ void ldsm4(uint32_t* r, uint32_t addr) {
    asm volatile("ldmatrix.sync.aligned.m8n8.x4.shared.b16 {%0,%1,%2,%3}, [%4];"
                 : "=r"(r[0]), "=r"(r[1]), "=r"(r[2]), "=r"(r[3]) : "r"(addr));
}
__device__ __forceinline__ void mma16816(float* d, const uint32_t* a,
                                         uint32_t b0, uint32_t b1) {
    asm volatile(
        "mma.sync.aligned.m16n8k16.row.col.f32.f16.f16.f32 "
        "{%0,%1,%2,%3}, {%4,%5,%6,%7}, {%8,%9}, {%0,%1,%2,%3};"
        : "+f"(d[0]), "+f"(d[1]), "+f"(d[2]), "+f"(d[3])
        : "r"(a[0]), "r"(a[1]), "r"(a[2]), "r"(a[3]), "r"(b0), "r"(b1));
}
__device__ __forceinline__ uint32_t pack2(__half a, __half b) {
    return (uint32_t)__half_as_ushort(a) | ((uint32_t)__half_as_ushort(b) << 16);
}

// ---------------------------------------------------------------------------
// Convert x -> (hi, lo) fp16. One warp per row, 8 rows per block.
// ---------------------------------------------------------------------------
__global__ void conv_x_kernel(const float4* __restrict__ x4) {
    int row  = blockIdx.x * 8 + (threadIdx.x >> 5);
    int lane = threadIdx.x & 31;
    const float4* p = x4 + (size_t)row * ROW_F4;
    uint2* hi = (uint2*)(g_xhi + (size_t)row * DIMV);
    uint2* lo = (uint2*)(g_xlo + (size_t)row * DIMV);
#pragma unroll
    for (int c = 0; c < 4; ++c) {
        float4 v = p[c * 32 + lane];
        __half hx = __float2half_rn(v.x), hy = __float2half_rn(v.y);
        __half hz = __float2half_rn(v.z), hw = __float2half_rn(v.w);
        __half lx = __float2half_rn(v.x - __half2float(hx));
        __half ly = __float2half_rn(v.y - __half2float(hy));
        __half lz = __float2half_rn(v.z - __half2float(hz));
        __half lw = __float2half_rn(v.w - __half2float(hw));
        uint2 H; H.x = pack2(hx, hy); H.y = pack2(hz, hw);
        uint2 L; L.x = pack2(lx, ly); L.y = pack2(lz, lw);
        hi[c * 32 + lane] = H;
        lo[c * 32 + lane] = L;
    }
}

// ---------------------------------------------------------------------------
// Convert codebook -> (hi, lo) fp16, compute e_sq (fp32), init g_best.
// ---------------------------------------------------------------------------
__global__ void conv_e_kernel(const float4* __restrict__ e4) {
    int row  = blockIdx.x * 8 + (threadIdx.x >> 5);
    int lane = threadIdx.x & 31;
    const float4* p = e4 + (size_t)row * ROW_F4;
    uint2* hi = (uint2*)(g_ehi + (size_t)row * DIMV);
    uint2* lo = (uint2*)(g_elo + (size_t)row * DIMV);
    float s = 0.f;
#pragma unroll
    for (int c = 0; c < 4; ++c) {
        float4 v = p[c * 32 + lane];
        s += v.x * v.x + v.y * v.y + v.z * v.z + v.w * v.w;
        __half hx = __float2half_rn(v.x), hy = __float2half_rn(v.y);
        __half hz = __float2half_rn(v.z), hw = __float2half_rn(v.w);
        __half lx = __float2half_rn(v.x - __half2float(hx));
        __half ly = __float2half_rn(v.y - __half2float(hy));
        __half lz = __float2half_rn(v.z - __half2float(hz));
        __half lw = __float2half_rn(v.w - __half2float(hw));
        uint2 H; H.x = pack2(hx, hy); H.y = pack2(hz, hw);
        uint2 L; L.x = pack2(lx, ly); L.y = pack2(lz, lw);
        hi[c * 32 + lane] = H;
        lo[c * 32 + lane] = L;
    }
#pragma unroll
    for (int off = 16; off; off >>= 1) s += __shfl_down_sync(0xFFFFFFFFu, s, off);
    if (lane == 0) { g_esq[row] = s; g_best[row] = 0ull; }
}

// ---------------------------------------------------------------------------
// Main fused split-fp16 GEMM (score = 2*x.E^T - e_sq) + per-row argmax.
// grid (64 ntiles, 64 mtiles), 256 threads (8 warps: 4 in M x 2 in N).
// Warp tile 32x64 = 2 x 8 mma.m16n8k16 tiles. K' = 1536 fp16 in 48 stages.
//   seg 0: A_hi * B_hi ; seg 1: A_hi * B_lo ; seg 2: A_lo * B_hi
// ---------------------------------------------------------------------------
__global__ __launch_bounds__(256, 2) void vq_mma() {
    extern __shared__ char smem[];
    const uint32_t sb = smem_u32(smem);
    const uint32_t sA = sb;
    const uint32_t sB = sb + NBUF * 8192;
    float* esq_s = (float*)(smem + 2 * NBUF * 8192);

    const int tid = threadIdx.x, lane = tid & 31, wid = tid >> 5;
    const int wm = wid >> 1, wn = wid & 1;
    const int mBase = blockIdx.y * BM, nBase = blockIdx.x * BN;

    if (tid < 32) ((float4*)esq_s)[tid] = ((const float4*)(g_esq + nBase))[tid];

    // cp.async item mapping: items i0=tid, i1=tid+256 of 512 16B-chunks/tile.
    const int rI0 = tid >> 2, cI = tid & 3, rI1 = (tid + 256) >> 2;
    const uint32_t d0 = rI0 * 64 + ((cI ^ ((rI0 >> 1) & 3)) << 4);
    const uint32_t d1 = rI1 * 64 + ((cI ^ ((rI1 >> 1) & 3)) << 4);

#define ISSUE(s)                                                               \
    {                                                                          \
        const int seg_ = (s) >> 4;                                             \
        const int k0_  = ((s) & 15) * 32;                                      \
        const uint32_t bo_ = ((s) & 3) * 8192;                                 \
        const __half* aS = (seg_ < 2) ? g_xhi : g_xlo;                         \
        const __half* bS = (seg_ == 1) ? g_elo : g_ehi;                        \
        cpasync16(sA + bo_ + d0, aS + (size_t)(mBase + rI0) * DIMV + k0_ + cI * 8); \
        cpasync16(sA + bo_ + d1, aS + (size_t)(mBase + rI1) * DIMV + k0_ + cI * 8); \
        cpasync16(sB + bo_ + d0, bS + (size_t)(nBase + rI0) * DIMV + k0_ + cI * 8); \
        cpasync16(sB + bo_ + d1, bS + (size_t)(nBase + rI1) * DIMV + k0_ + cI * 8); \
        asm volatile("cp.async.commit_group;" ::: "memory");                   \
    }

    float acc[2][8][4];
#pragma unroll
    for (int a = 0; a < 2; ++a)
#pragma unroll
        for (int b = 0; b < 8; ++b)
#pragma unroll
            for (int c = 0; c < 4; ++c) acc[a][b][c] = 0.f;

    // ldmatrix per-lane row bases (rows fixed per thread; chunk varies by k).
    const int hi16 = lane >> 4;
    uint32_t aRow[2], aSw[2], bRow[4], bSw[4];
#pragma unroll
    for (int mt = 0; mt < 2; ++mt) {
        int r = wm * 32 + mt * 16 + (lane & 15);
        aRow[mt] = (uint32_t)r * 64; aSw[mt] = (r >> 1) & 3;
    }
#pragma unroll
    for (int nt2 = 0; nt2 < 4; ++nt2) {
        int r = wn * 64 + nt2 * 16 + (lane & 15);
        bRow[nt2] = (uint32_t)r * 64; bSw[nt2] = (r >> 1) & 3;
    }

    ISSUE(0); ISSUE(1); ISSUE(2);

    for (int s = 0; s < KSTAGES; ++s) {
        if (s + 3 < KSTAGES)
            asm volatile("cp.async.wait_group 2;" ::: "memory");
        else
            asm volatile("cp.async.wait_group 0;" ::: "memory");
        __syncthreads();

        const uint32_t bo = (s & 3) * 8192;
#pragma unroll
        for (int kk = 0; kk < 2; ++kk) {
            const int ch = kk * 2 + hi16;
            uint32_t a0[4], a1[4], bb[4][4];
            ldsm4(a0, sA + bo + aRow[0] + (((ch ^ aSw[0]) & 3) << 4));
            ldsm4(a1, sA + bo + aRow[1] + (((ch ^ aSw[1]) & 3) << 4));
#pragma unroll
            for (int nt2 = 0; nt2 < 4; ++nt2)
                ldsm4(bb[nt2], sB + bo + bRow[nt2] + (((ch ^ bSw[nt2]) & 3) << 4));
#pragma unroll
            for (int nt = 0; nt < 8; ++nt) {
                const int nt2 = nt >> 1, od = nt & 1;
                mma16816(acc[0][nt], a0, bb[nt2][od], bb[nt2][2 + od]);
                mma16816(acc[1][nt], a1, bb[nt2][od], bb[nt2][2 + od]);
            }
        }
        if (s + 3 < KSTAGES) ISSUE(s + 3);
    }
#undef ISSUE

    // Epilogue: score = 2*acc - esq; per-row argmax; merge via packed atomicMax.
    const int q = lane & 3, qr = lane >> 2;
#pragma unroll
    for (int mt = 0; mt < 2; ++mt) {
#pragma unroll
        for (int h = 0; h < 2; ++h) {
            const int rowG = mBase + wm * 32 + mt * 16 + h * 8 + qr;
            float bv = -3.4e38f; int bi = 0;
#pragma unroll
            for (int nt = 0; nt < 8; ++nt) {
#pragma unroll
                for (int j = 0; j < 2; ++j) {
                    const int col = wn * 64 + nt * 8 + q * 2 + j;
                    float sc = 2.f * acc[mt][nt][h * 2 + j] - esq_s[col];
                    if (sc > bv) { bv = sc; bi = nBase + col; }
                }
            }
#pragma unroll
            for (int off = 1; off <= 2; off <<= 1) {
                float ov = __shfl_xor_sync(0xFFFFFFFFu, bv, off);
                int   oi = __shfl_xor_sync(0xFFFFFFFFu, bi, off);
                if (ov > bv || (ov == bv && oi < bi)) { bv = ov; bi = oi; }
            }
            if (q == 0) {
                uint32_t b = __float_as_uint(bv);
                b ^= (b >> 31) ? 0xFFFFFFFFu : 0x80000000u;
                unsigned long long key =
                    ((unsigned long long)b << 32) | (uint32_t)(~bi);
                atomicMax(&g_best[rowG], key);
            }
        }
    }
}

// ---------------------------------------------------------------------------
// Gather chosen codewords (exact fp32 source) + write indices.
// ---------------------------------------------------------------------------
__global__ void gather_kernel(const float4* __restrict__ e4, float* __restrict__ out,
                              int nRows) {
    int row  = blockIdx.x * 8 + (threadIdx.x >> 5);
    int lane = threadIdx.x & 31;
    int idx  = (int)(~((uint32_t)g_best[row]));
    const float4* src = e4 + (size_t)idx * ROW_F4;
    float4* dst = (float4*)out + (size_t)row * ROW_F4;
#pragma unroll
    for (int c = 0; c < 4; ++c) dst[lane + 32 * c] = src[lane + 32 * c];
    if (lane == 0) out[(size_t)nRows * DIMV + row] = (float)idx;
}

// ---------------------------------------------------------------------------
extern "C" void kernel_launch(void* const* d_in, const int* in_sizes, int n_in,
                              void* d_out, int out_size) {
    const float4* x4 = (const float4*)d_in[0];
    const float4* e4 = (const float4*)d_in[1];
    float* out = (float*)d_out;
    const int nRows = in_sizes[0] / DIMV;   // 8192
    const int kRows = in_sizes[1] / DIMV;   // 8192

    static int smemSet = 0;
    if (!smemSet) {
        cudaFuncSetAttribute(vq_mma, cudaFuncAttributeMaxDynamicSharedMemorySize, SMEMSZ);
        smemSet = 1;
    }

    conv_x_kernel<<<nRows / 8, 256>>>(x4);
    conv_e_kernel<<<kRows / 8, 256>>>(e4);
    vq_mma<<<dim3(64, 64), 256, SMEMSZ>>>();
    gather_kernel<<<nRows / 8, 256>>>(e4, out, nRows);
}

// round 4
// speedup vs baseline: 6.8909x; 1.7746x over previous
#include <cuda_runtime.h>
#include <cuda_fp16.h>
#include <cstdint>

// Problem constants: x [8192,512] fp32, codebook [8192,512] fp32.
#define DIMV    512
#define ROW_F4  128
#define KCB     8192
#define NROWSC  8192
#define BM      128
#define BN      128
#define KSTAGES 16          // K = 512 fp16 (hi-part only), 32 per stage
#define NBUF    4
#define SMEMSZ  (2*NBUF*8192 + 512)   // A(32KB) + B(32KB) + esq(512B)
#define TILES8  (KCB / 8)   // 1024 eight-code tiles
#define EPS     1.0f        // pruning slack (>= 20x the approx-score error)

// Static scratch (module-load allocations, no runtime allocs).
__device__ __align__(16) __half g_xh[NROWSC * DIMV];
__device__ __align__(16) __half g_eh[KCB * DIMV];
__device__ float g_esq[KCB];
__device__ float g_tileMax[NROWSC * TILES8];   // 32MB: per (row, 8-code tile) approx max

__device__ __forceinline__ uint32_t smem_u32(const void* p) {
    uint32_t a;
    asm("{ .reg .u64 t; cvta.to.shared.u64 t, %1; cvt.u32.u64 %0, t; }" : "=r"(a) : "l"(p));
    return a;
}
__device__ __forceinline__ void cpasync16(uint32_t dst, const void* src) {
    asm volatile("cp.async.cg.shared.global [%0], [%1], 16;"
                 :: "r"(dst), "l"(__cvta_generic_to_global(src)) : "memory");
}
__device__ __forceinline__ void ldsm4(uint32_t* r, uint32_t addr) {
    asm volatile("ldmatrix.sync.aligned.m8n8.x4.shared.b16 {%0,%1,%2,%3}, [%4];"
                 : "=r"(r[0]), "=r"(r[1]), "=r"(r[2]), "=r"(r[3]) : "r"(addr));
}
__device__ __forceinline__ void mma16816(float* d, const uint32_t* a,
                                         uint32_t b0, uint32_t b1) {
    asm volatile(
        "mma.sync.aligned.m16n8k16.row.col.f32.f16.f16.f32 "
        "{%0,%1,%2,%3}, {%4,%5,%6,%7}, {%8,%9}, {%0,%1,%2,%3};"
        : "+f"(d[0]), "+f"(d[1]), "+f"(d[2]), "+f"(d[3])
        : "r"(a[0]), "r"(a[1]), "r"(a[2]), "r"(a[3]), "r"(b0), "r"(b1));
}
__device__ __forceinline__ uint32_t pack2(__half a, __half b) {
    return (uint32_t)__half_as_ushort(a) | ((uint32_t)__half_as_ushort(b) << 16);
}

// ---------------------------------------------------------------------------
// x -> fp16 hi part. One warp per row, 8 rows per block.
// ---------------------------------------------------------------------------
__global__ void conv_x_kernel(const float4* __restrict__ x4) {
    int row  = blockIdx.x * 8 + (threadIdx.x >> 5);
    int lane = threadIdx.x & 31;
    const float4* p = x4 + (size_t)row * ROW_F4;
    uint2* hi = (uint2*)(g_xh + (size_t)row * DIMV);
#pragma unroll
    for (int c = 0; c < 4; ++c) {
        float4 v = p[c * 32 + lane];
        uint2 H;
        H.x = pack2(__float2half_rn(v.x), __float2half_rn(v.y));
        H.y = pack2(__float2half_rn(v.z), __float2half_rn(v.w));
        hi[c * 32 + lane] = H;
    }
}

// ---------------------------------------------------------------------------
// codebook -> fp16 hi part + exact fp32 e_sq.
// ---------------------------------------------------------------------------
__global__ void conv_e_kernel(const float4* __restrict__ e4) {
    int row  = blockIdx.x * 8 + (threadIdx.x >> 5);
    int lane = threadIdx.x & 31;
    const float4* p = e4 + (size_t)row * ROW_F4;
    uint2* hi = (uint2*)(g_eh + (size_t)row * DIMV);
    float s = 0.f;
#pragma unroll
    for (int c = 0; c < 4; ++c) {
        float4 v = p[c * 32 + lane];
        s += v.x * v.x + v.y * v.y + v.z * v.z + v.w * v.w;
        uint2 H;
        H.x = pack2(__float2half_rn(v.x), __float2half_rn(v.y));
        H.y = pack2(__float2half_rn(v.z), __float2half_rn(v.w));
        hi[c * 32 + lane] = H;
    }
#pragma unroll
    for (int off = 16; off; off >>= 1) s += __shfl_down_sync(0xFFFFFFFFu, s, off);
    if (lane == 0) g_esq[row] = s;
}

// ---------------------------------------------------------------------------
// Pass 1: fp16 hi*hi GEMM (approx score = 2*x.E^T - e_sq), store per-8-code
// tile maxima. grid (64 ntiles, 64 mtiles), 256 threads (8 warps: 4M x 2N).
// ---------------------------------------------------------------------------
__global__ __launch_bounds__(256, 2) void vq_mma() {
    extern __shared__ char smem[];
    const uint32_t sb = smem_u32(smem);
    const uint32_t sA = sb;
    const uint32_t sB = sb + NBUF * 8192;
    float* esq_s = (float*)(smem + 2 * NBUF * 8192);

    const int tid = threadIdx.x, lane = tid & 31, wid = tid >> 5;
    const int wm = wid >> 1, wn = wid & 1;
    const int mBase = blockIdx.y * BM, nBase = blockIdx.x * BN;

    if (tid < 32) ((float4*)esq_s)[tid] = ((const float4*)(g_esq + nBase))[tid];

    const int rI0 = tid >> 2, cI = tid & 3, rI1 = (tid + 256) >> 2;
    const uint32_t d0 = rI0 * 64 + ((cI ^ ((rI0 >> 1) & 3)) << 4);
    const uint32_t d1 = rI1 * 64 + ((cI ^ ((rI1 >> 1) & 3)) << 4);

#define ISSUE(s)                                                               \
    {                                                                          \
        const int k0_  = (s) * 32;                                             \
        const uint32_t bo_ = ((s) & 3) * 8192;                                 \
        cpasync16(sA + bo_ + d0, g_xh + (size_t)(mBase + rI0) * DIMV + k0_ + cI * 8); \
        cpasync16(sA + bo_ + d1, g_xh + (size_t)(mBase + rI1) * DIMV + k0_ + cI * 8); \
        cpasync16(sB + bo_ + d0, g_eh + (size_t)(nBase + rI0) * DIMV + k0_ + cI * 8); \
        cpasync16(sB + bo_ + d1, g_eh + (size_t)(nBase + rI1) * DIMV + k0_ + cI * 8); \
        asm volatile("cp.async.commit_group;" ::: "memory");                   \
    }

    float acc[2][8][4];
#pragma unroll
    for (int a = 0; a < 2; ++a)
#pragma unroll
        for (int b = 0; b < 8; ++b)
#pragma unroll
            for (int c = 0; c < 4; ++c) acc[a][b][c] = 0.f;

    const int hi16 = lane >> 4;
    uint32_t aRow[2], aSw[2], bRow[4], bSw[4];
#pragma unroll
    for (int mt = 0; mt < 2; ++mt) {
        int r = wm * 32 + mt * 16 + (lane & 15);
        aRow[mt] = (uint32_t)r * 64; aSw[mt] = (r >> 1) & 3;
    }
#pragma unroll
    for (int nt2 = 0; nt2 < 4; ++nt2) {
        int r = wn * 64 + nt2 * 16 + (lane & 15);
        bRow[nt2] = (uint32_t)r * 64; bSw[nt2] = (r >> 1) & 3;
    }

    ISSUE(0); ISSUE(1); ISSUE(2);

    for (int s = 0; s < KSTAGES; ++s) {
        if (s + 3 < KSTAGES)
            asm volatile("cp.async.wait_group 2;" ::: "memory");
        else
            asm volatile("cp.async.wait_group 0;" ::: "memory");
        __syncthreads();

        const uint32_t bo = (s & 3) * 8192;
#pragma unroll
        for (int kk = 0; kk < 2; ++kk) {
            const int ch = kk * 2 + hi16;
            uint32_t a0[4], a1[4], bb[4][4];
            ldsm4(a0, sA + bo + aRow[0] + (((ch ^ aSw[0]) & 3) << 4));
            ldsm4(a1, sA + bo + aRow[1] + (((ch ^ aSw[1]) & 3) << 4));
#pragma unroll
            for (int nt2 = 0; nt2 < 4; ++nt2)
                ldsm4(bb[nt2], sB + bo + bRow[nt2] + (((ch ^ bSw[nt2]) & 3) << 4));
#pragma unroll
            for (int nt = 0; nt < 8; ++nt) {
                const int nt2 = nt >> 1, od = nt & 1;
                mma16816(acc[0][nt], a0, bb[nt2][od], bb[nt2][2 + od]);
                mma16816(acc[1][nt], a1, bb[nt2][od], bb[nt2][2 + od]);
            }
        }
        if (s + 3 < KSTAGES) ISSUE(s + 3);
    }
#undef ISSUE

    // Epilogue: per-(row, 8-code tile) max of approx score.
    // Thread quad (q=0..3) covers 8 cols of tile nt; 2 shuffles reduce over quad.
    const int q = lane & 3, qr = lane >> 2;
#pragma unroll
    for (int mt = 0; mt < 2; ++mt) {
#pragma unroll
        for (int h = 0; h < 2; ++h) {
            const int rowG = mBase + wm * 32 + mt * 16 + h * 8 + qr;
            float* dst = g_tileMax + (size_t)rowG * TILES8 + blockIdx.x * 16 + wn * 8;
#pragma unroll
            for (int nt = 0; nt < 8; ++nt) {
                const int col = wn * 64 + nt * 8 + q * 2;
                float s0 = 2.f * acc[mt][nt][h * 2 + 0] - esq_s[col];
                float s1 = 2.f * acc[mt][nt][h * 2 + 1] - esq_s[col + 1];
                float bv = fmaxf(s0, s1);
                bv = fmaxf(bv, __shfl_xor_sync(0xFFFFFFFFu, bv, 1));
                bv = fmaxf(bv, __shfl_xor_sync(0xFFFFFFFFu, bv, 2));
                if (q == 0) dst[nt] = bv;
            }
        }
    }
}

// ---------------------------------------------------------------------------
// Pass 2: per row — find candidate tiles within EPS of max, exact fp32
// rescore, argmax (ties -> smallest index), gather + write index.
// One 256-thread CTA per row.
// ---------------------------------------------------------------------------
__global__ __launch_bounds__(256, 4) void rescore_kernel(
        const float4* __restrict__ x4, const float4* __restrict__ e4,
        float* __restrict__ out, int nRows) {
    __shared__ float xs[DIMV];
    __shared__ float redbuf[8];
    __shared__ float warpV[8];
    __shared__ int   warpI[8];
    __shared__ int   list[128];
    __shared__ int   cnt;
    __shared__ float rowmaxS;
    __shared__ int   finalIdx;

    const int row = blockIdx.x;
    const int tid = threadIdx.x, lane = tid & 31, wid = tid >> 5;

    if (tid == 0) cnt = 0;
    if (tid < 128) ((float4*)xs)[tid] = x4[(size_t)row * ROW_F4 + tid];

    // Row max over 1024 tile maxima (4 per thread).
    const float4 tv = ((const float4*)(g_tileMax + (size_t)row * TILES8))[tid];
    float m = fmaxf(fmaxf(tv.x, tv.y), fmaxf(tv.z, tv.w));
#pragma unroll
    for (int off = 16; off; off >>= 1)
        m = fmaxf(m, __shfl_xor_sync(0xFFFFFFFFu, m, off));
    if (lane == 0) redbuf[wid] = m;
    __syncthreads();
    if (tid == 0) {
        float r = redbuf[0];
#pragma unroll
        for (int i = 1; i < 8; ++i) r = fmaxf(r, redbuf[i]);
        rowmaxS = r;
    }
    __syncthreads();

    const float thr = rowmaxS - EPS;
    {
        const float tvv[4] = {tv.x, tv.y, tv.z, tv.w};
#pragma unroll
        for (int j = 0; j < 4; ++j) {
            if (tvv[j] >= thr) {
                int p = atomicAdd(&cnt, 1);
                if (p < 128) list[p] = tid * 4 + j;
            }
        }
    }
    __syncthreads();
    const int n = (cnt < 128) ? cnt : 128;

    // Exact rescore: warp handles one candidate tile (8 codes; 4 lanes/code).
    float bv = -3.4e38f; int bi = 0x7FFFFFFF;
    const int qq = lane & 3;
    for (int i = wid; i < n; i += 8) {
        const int code = list[i] * 8 + (lane >> 2);
        const float4* ep = e4 + (size_t)code * ROW_F4;
        float d = 0.f;
#pragma unroll
        for (int c = 0; c < 32; ++c) {
            float4 ev = ep[qq * 32 + c];
            float4 xv = ((const float4*)xs)[qq * 32 + c];
            d += ev.x * xv.x + ev.y * xv.y + ev.z * xv.z + ev.w * xv.w;
        }
        d += __shfl_xor_sync(0xFFFFFFFFu, d, 1);
        d += __shfl_xor_sync(0xFFFFFFFFu, d, 2);
        if (qq == 0) {
            float s = 2.f * d - g_esq[code];
            if (s > bv || (s == bv && code < bi)) { bv = s; bi = code; }
        }
    }
#pragma unroll
    for (int off = 16; off; off >>= 1) {
        float ov = __shfl_xor_sync(0xFFFFFFFFu, bv, off);
        int   oi = __shfl_xor_sync(0xFFFFFFFFu, bi, off);
        if (ov > bv || (ov == bv && oi < bi)) { bv = ov; bi = oi; }
    }
    if (lane == 0) { warpV[wid] = bv; warpI[wid] = bi; }
    __syncthreads();
    if (tid == 0) {
        float fv = warpV[0]; int fi = warpI[0];
#pragma unroll
        for (int i = 1; i < 8; ++i) {
            if (warpV[i] > fv || (warpV[i] == fv && warpI[i] < fi)) {
                fv = warpV[i]; fi = warpI[i];
            }
        }
        finalIdx = fi;
    }
    __syncthreads();

    const int idx = finalIdx;
    if (tid < 128)
        ((float4*)out)[(size_t)row * ROW_F4 + tid] = e4[(size_t)idx * ROW_F4 + tid];
    if (tid == 0) out[(size_t)nRows * DIMV + row] = (float)idx;
}

// ---------------------------------------------------------------------------
extern "C" void kernel_launch(void* const* d_in, const int* in_sizes, int n_in,
                              void* d_out, int out_size) {
    const float4* x4 = (const float4*)d_in[0];
    const float4* e4 = (const float4*)d_in[1];
    float* out = (float*)d_out;
    const int nRows = in_sizes[0] / DIMV;   // 8192
    const int kRows = in_sizes[1] / DIMV;   // 8192

    static int smemSet = 0;
    if (!smemSet) {
        cudaFuncSetAttribute(vq_mma, cudaFuncAttributeMaxDynamicSharedMemorySize, SMEMSZ);
        smemSet = 1;
    }

    conv_x_kernel<<<nRows / 8, 256>>>(x4);
    conv_e_kernel<<<kRows / 8, 256>>>(e4);
    vq_mma<<<dim3(64, 64), 256, SMEMSZ>>>();
    rescore_kernel<<<nRows, 256>>>(x4, e4, out, nRows);
}

// round 6
// speedup vs baseline: 7.0472x; 1.0227x over previous
#include <cuda_runtime.h>
#include <cuda_fp16.h>
#include <cstdint>

// Problem constants: x [8192,512] fp32, codebook [8192,512] fp32.
#define DIMV    512
#define ROW_F4  128
#define KCB     8192
#define NROWSC  8192
#define BM      128
#define BN      256
#define KSTAGES 16            // K = 512 fp16 (hi part), 32 per stage
#define NBUF    4
#define STAGEB  24576         // A 8KB + B 16KB per stage
#define SMEMSZ  (NBUF*STAGEB + 1024)
#define TILES8  (KCB / 8)     // 1024 eight-code tiles per row
#define EPS     1.0f          // pruning slack (>> approx-score error)

__device__ __align__(16) __half g_xh[NROWSC * DIMV];
__device__ __align__(16) __half g_eh[KCB * DIMV];
__device__ float g_esq[KCB];
__device__ float g_tileMax[NROWSC * TILES8];   // 32MB

__device__ __forceinline__ uint32_t smem_u32(const void* p) {
    uint32_t a;
    asm("{ .reg .u64 t; cvta.to.shared.u64 t, %1; cvt.u32.u64 %0, t; }" : "=r"(a) : "l"(p));
    return a;
}
__device__ __forceinline__ void cpasync16(uint32_t dst, const void* src) {
    asm volatile("cp.async.cg.shared.global [%0], [%1], 16;"
                 :: "r"(dst), "l"(__cvta_generic_to_global(src)) : "memory");
}
__device__ __forceinline__ void ldsm4(uint32_t* r, uint32_t addr) {
    asm volatile("ldmatrix.sync.aligned.m8n8.x4.shared.b16 {%0,%1,%2,%3}, [%4];"
                 : "=r"(r[0]), "=r"(r[1]), "=r"(r[2]), "=r"(r[3]) : "r"(addr));
}
__device__ __forceinline__ void mma16816(float* d, const uint32_t* a,
                                         uint32_t b0, uint32_t b1) {
    asm volatile(
        "mma.sync.aligned.m16n8k16.row.col.f32.f16.f16.f32 "
        "{%0,%1,%2,%3}, {%4,%5,%6,%7}, {%8,%9}, {%0,%1,%2,%3};"
        : "+f"(d[0]), "+f"(d[1]), "+f"(d[2]), "+f"(d[3])
        : "r"(a[0]), "r"(a[1]), "r"(a[2]), "r"(a[3]), "r"(b0), "r"(b1));
}
__device__ __forceinline__ uint32_t pack2(__half a, __half b) {
    return (uint32_t)__half_as_ushort(a) | ((uint32_t)__half_as_ushort(b) << 16);
}

// ---------------------------------------------------------------------------
__global__ void conv_x_kernel(const float4* __restrict__ x4) {
    int row  = blockIdx.x * 8 + (threadIdx.x >> 5);
    int lane = threadIdx.x & 31;
    const float4* p = x4 + (size_t)row * ROW_F4;
    uint2* hi = (uint2*)(g_xh + (size_t)row * DIMV);
#pragma unroll
    for (int c = 0; c < 4; ++c) {
        float4 v = p[c * 32 + lane];
        uint2 H;
        H.x = pack2(__float2half_rn(v.x), __float2half_rn(v.y));
        H.y = pack2(__float2half_rn(v.z), __float2half_rn(v.w));
        hi[c * 32 + lane] = H;
    }
}

__global__ void conv_e_kernel(const float4* __restrict__ e4) {
    int row  = blockIdx.x * 8 + (threadIdx.x >> 5);
    int lane = threadIdx.x & 31;
    const float4* p = e4 + (size_t)row * ROW_F4;
    uint2* hi = (uint2*)(g_eh + (size_t)row * DIMV);
    float s = 0.f;
#pragma unroll
    for (int c = 0; c < 4; ++c) {
        float4 v = p[c * 32 + lane];
        s += v.x * v.x + v.y * v.y + v.z * v.z + v.w * v.w;
        uint2 H;
        H.x = pack2(__float2half_rn(v.x), __float2half_rn(v.y));
        H.y = pack2(__float2half_rn(v.z), __float2half_rn(v.w));
        hi[c * 32 + lane] = H;
    }
#pragma unroll
    for (int off = 16; off; off >>= 1) s += __shfl_down_sync(0xFFFFFFFFu, s, off);
    if (lane == 0) g_esq[row] = s;
}

// ---------------------------------------------------------------------------
// Pass 1: fp16 hi*hi GEMM, per-(row, 8-code tile) approx-score maxima.
// grid (32 ntiles, 64 mtiles), 256 threads = 8 warps (2M x 4N), warp 64x64.
// ---------------------------------------------------------------------------
__global__ __launch_bounds__(256, 1) void vq_mma() {
    extern __shared__ char smem[];
    const uint32_t sb = smem_u32(smem);
    float* esq_s = (float*)(smem + NBUF * STAGEB);

    const int tid = threadIdx.x, lane = tid & 31, wid = tid >> 5;
    const int wm = wid >> 2, wn = wid & 3;
    const int mBase = blockIdx.y * BM, nBase = blockIdx.x * BN;

    if (tid < 64) ((float4*)esq_s)[tid] = ((const float4*)(g_esq + nBase))[tid];

    // cp.async mapping: 1536 16B chunks/stage. col group cI constant per thread.
    const int rr = tid >> 2, cI = tid & 3;
    const uint32_t dA0 = (uint32_t)rr * 64 + ((cI ^ ((rr >> 1) & 3)) << 4);

#define ISSUE(s)                                                               \
    {                                                                          \
        const int k0_ = (s) * 32;                                              \
        const uint32_t st_ = sb + ((s) & 3) * STAGEB;                          \
        cpasync16(st_ + dA0,        g_xh + (size_t)(mBase + rr) * DIMV + k0_ + cI * 8);      \
        cpasync16(st_ + dA0 + 4096, g_xh + (size_t)(mBase + 64 + rr) * DIMV + k0_ + cI * 8); \
        const uint32_t bb_ = st_ + 8192 + dA0;                                 \
        _Pragma("unroll")                                                      \
        for (int j = 0; j < 4; ++j)                                            \
            cpasync16(bb_ + j * 4096,                                          \
                      g_eh + (size_t)(nBase + j * 64 + rr) * DIMV + k0_ + cI * 8); \
        asm volatile("cp.async.commit_group;" ::: "memory");                   \
    }

    float acc[4][8][4];
#pragma unroll
    for (int a = 0; a < 4; ++a)
#pragma unroll
        for (int b = 0; b < 8; ++b)
#pragma unroll
            for (int c = 0; c < 4; ++c) acc[a][b][c] = 0.f;

    // ldsm bases: swizzle group depends only on (lane&15).
    const int l15 = lane & 15, hi16 = lane >> 4;
    const uint32_t swz = (uint32_t)((l15 >> 1) & 3);
    uint32_t aBase[4], bBase[4];
#pragma unroll
    for (int mt = 0; mt < 4; ++mt)
        aBase[mt] = (uint32_t)(wm * 64 + mt * 16 + l15) * 64;
#pragma unroll
    for (int nt2 = 0; nt2 < 4; ++nt2)
        bBase[nt2] = 8192u + (uint32_t)(wn * 64 + nt2 * 16 + l15) * 64;

    ISSUE(0); ISSUE(1); ISSUE(2);

    for (int s = 0; s < KSTAGES; ++s) {
        if (s + 3 < KSTAGES)
            asm volatile("cp.async.wait_group 2;" ::: "memory");
        else
            asm volatile("cp.async.wait_group 0;" ::: "memory");
        __syncthreads();

        const uint32_t st = sb + (s & 3) * STAGEB;
#pragma unroll
        for (int kk = 0; kk < 2; ++kk) {
            const uint32_t coloff = (((uint32_t)(kk * 2 + hi16) ^ swz) & 3) << 4;
            uint32_t a[4][4], b[4][4];
#pragma unroll
            for (int mt = 0; mt < 4; ++mt) ldsm4(a[mt], st + aBase[mt] + coloff);
#pragma unroll
            for (int nt2 = 0; nt2 < 4; ++nt2) ldsm4(b[nt2], st + bBase[nt2] + coloff);
#pragma unroll
            for (int mt = 0; mt < 4; ++mt)
#pragma unroll
                for (int nt = 0; nt < 8; ++nt) {
                    const int nt2 = nt >> 1, od = nt & 1;
                    mma16816(acc[mt][nt], a[mt], b[nt2][od], b[nt2][2 + od]);
                }
        }
        if (s + 3 < KSTAGES) ISSUE(s + 3);
    }
#undef ISSUE

    // Epilogue: per-(row, 8-code tile) max of approx score (quad-reduced).
    const int q = lane & 3, qr = lane >> 2;
#pragma unroll
    for (int mt = 0; mt < 4; ++mt) {
#pragma unroll
        for (int h = 0; h < 2; ++h) {
            const int rowG = mBase + wm * 64 + mt * 16 + h * 8 + qr;
            float* dst = g_tileMax + (size_t)rowG * TILES8 + blockIdx.x * 32 + wn * 8;
#pragma unroll
            for (int nt = 0; nt < 8; ++nt) {
                const int col = wn * 64 + nt * 8 + q * 2;
                float s0 = 2.f * acc[mt][nt][h * 2 + 0] - esq_s[col];
                float s1 = 2.f * acc[mt][nt][h * 2 + 1] - esq_s[col + 1];
                float bv = fmaxf(s0, s1);
                bv = fmaxf(bv, __shfl_xor_sync(0xFFFFFFFFu, bv, 1));
                bv = fmaxf(bv, __shfl_xor_sync(0xFFFFFFFFu, bv, 2));
                if (q == 0) dst[nt] = bv;
            }
        }
    }
}

// ---------------------------------------------------------------------------
// Pass 2: warp-per-row, barrier-free. Scan tile maxima, rescore candidate
// tiles exactly in fp32, argmax (ties -> smallest idx), gather + index.
// ---------------------------------------------------------------------------
__global__ __launch_bounds__(256) void rescore_kernel(
        const float4* __restrict__ x4, const float4* __restrict__ e4,
        float* __restrict__ out, int nRows) {
    __shared__ float xs[8][DIMV];

    const int tid = threadIdx.x, lane = tid & 31, wid = tid >> 5;
    const int row = blockIdx.x * 8 + wid;

    // Stage this row's x into the warp's smem slice.
    float4* xs4 = (float4*)xs[wid];
#pragma unroll
    for (int c = 0; c < 4; ++c)
        xs4[lane + 32 * c] = x4[(size_t)row * ROW_F4 + lane + 32 * c];
    __syncwarp();

    // Load 1024 tile maxima (32 per lane, coalesced f4) and find row max.
    const float4* tm4 = (const float4*)(g_tileMax + (size_t)row * TILES8);
    float4 tv[8];
    float m = -3.4e38f;
#pragma unroll
    for (int j = 0; j < 8; ++j) {
        tv[j] = tm4[j * 32 + lane];
        m = fmaxf(m, fmaxf(fmaxf(tv[j].x, tv[j].y), fmaxf(tv[j].z, tv[j].w)));
    }
#pragma unroll
    for (int off = 16; off; off >>= 1)
        m = fmaxf(m, __shfl_xor_sync(0xFFFFFFFFu, m, off));
    const float thr = m - EPS;

    float bv = -3.4e38f; int bi = 0x7FFFFFFF;
    const int qq = lane & 3, code8 = lane >> 2;

#pragma unroll
    for (int j = 0; j < 8; ++j) {
        bool any = (tv[j].x >= thr) | (tv[j].y >= thr) |
                   (tv[j].z >= thr) | (tv[j].w >= thr);
        unsigned mask = __ballot_sync(0xFFFFFFFFu, any);
        while (mask) {
            const int src = __ffs(mask) - 1;
            mask &= mask - 1;
            float cc[4];
            cc[0] = __shfl_sync(0xFFFFFFFFu, tv[j].x, src);
            cc[1] = __shfl_sync(0xFFFFFFFFu, tv[j].y, src);
            cc[2] = __shfl_sync(0xFFFFFFFFu, tv[j].z, src);
            cc[3] = __shfl_sync(0xFFFFFFFFu, tv[j].w, src);
#pragma unroll
            for (int comp = 0; comp < 4; ++comp) {
                if (cc[comp] < thr) continue;
                const int t = (j * 32 + src) * 4 + comp;
                // Exact fp32 rescore of tile t (8 codes, 4 lanes per code).
                const int code = t * 8 + code8;
                const float4* ep = e4 + (size_t)code * ROW_F4;
                float d = 0.f;
#pragma unroll
                for (int c = 0; c < 32; ++c) {
                    float4 ev = ep[qq * 32 + c];
                    float4 xv = xs4[qq * 32 + c];
                    d += ev.x * xv.x + ev.y * xv.y + ev.z * xv.z + ev.w * xv.w;
                }
                d += __shfl_xor_sync(0xFFFFFFFFu, d, 1);
                d += __shfl_xor_sync(0xFFFFFFFFu, d, 2);
                if (qq == 0) {
                    float s = 2.f * d - g_esq[code];
                    if (s > bv || (s == bv && code < bi)) { bv = s; bi = code; }
                }
            }
        }
    }

    // Warp-wide argmax (ties -> smallest index).
#pragma unroll
    for (int off = 16; off; off >>= 1) {
        float ov = __shfl_xor_sync(0xFFFFFFFFu, bv, off);
        int   oi = __shfl_xor_sync(0xFFFFFFFFu, bi, off);
        if (ov > bv || (ov == bv && oi < bi)) { bv = ov; bi = oi; }
    }

    // Gather codeword + write index.
    const float4* src = e4 + (size_t)bi * ROW_F4;
    float4* dst = (float4*)out + (size_t)row * ROW_F4;
#pragma unroll
    for (int c = 0; c < 4; ++c) dst[lane + 32 * c] = src[lane + 32 * c];
    if (lane == 0) out[(size_t)nRows * DIMV + row] = (float)bi;
}

// ---------------------------------------------------------------------------
extern "C" void kernel_launch(void* const* d_in, const int* in_sizes, int n_in,
                              void* d_out, int out_size) {
    const float4* x4 = (const float4*)d_in[0];
    const float4* e4 = (const float4*)d_in[1];
    float* out = (float*)d_out;
    const int nRows = in_sizes[0] / DIMV;   // 8192
    const int kRows = in_sizes[1] / DIMV;   // 8192

    static int smemSet = 0;
    if (!smemSet) {
        cudaFuncSetAttribute(vq_mma, cudaFuncAttributeMaxDynamicSharedMemorySize, SMEMSZ);
        smemSet = 1;
    }

    conv_x_kernel<<<nRows / 8, 256>>>(x4);
    conv_e_kernel<<<kRows / 8, 256>>>(e4);
    vq_mma<<<dim3(KCB / BN, nRows / BM), 256, SMEMSZ>>>();
    rescore_kernel<<<nRows / 8, 256>>>(x4, e4, out, nRows);
}

// round 7
// speedup vs baseline: 7.5880x; 1.0767x over previous
#include <cuda_runtime.h>
#include <cuda_fp16.h>
#include <cstdint>

// Problem constants: x [8192,512] fp32, codebook [8192,512] fp32.
#define DIMV    512
#define ROW_F4  128
#define KCB     8192
#define NROWSC  8192
#define BM      128
#define BN      128
#define KSTAGES 16            // K = 512 fp16 (hi part), 32 per stage
#define NBUF    4
#define STAGEB  16384         // A 8KB + B 8KB per stage
#define SMEMSZ  (NBUF*STAGEB + 1024)
#define TILES8  (KCB / 8)     // 1024 eight-code tiles per row
#define EPS     1.0f          // pruning slack (>> approx-score error)

__device__ __align__(16) __half g_xh[NROWSC * DIMV];
__device__ __align__(16) __half g_eh[KCB * DIMV];
__device__ float g_esq[KCB];
__device__ float g_tileMax[NROWSC * TILES8];   // 32MB

__device__ __forceinline__ uint32_t smem_u32(const void* p) {
    uint32_t a;
    asm("{ .reg .u64 t; cvta.to.shared.u64 t, %1; cvt.u32.u64 %0, t; }" : "=r"(a) : "l"(p));
    return a;
}
__device__ __forceinline__ void cpasync16(uint32_t dst, const void* src) {
    asm volatile("cp.async.cg.shared.global [%0], [%1], 16;"
                 :: "r"(dst), "l"(__cvta_generic_to_global(src)) : "memory");
}
__device__ __forceinline__ void ldsm4(uint32_t* r, uint32_t addr) {
    asm volatile("ldmatrix.sync.aligned.m8n8.x4.shared.b16 {%0,%1,%2,%3}, [%4];"
                 : "=r"(r[0]), "=r"(r[1]), "=r"(r[2]), "=r"(r[3]) : "r"(addr));
}
__device__ __forceinline__ void mma16816(float* d, const uint32_t* a,
                                         uint32_t b0, uint32_t b1) {
    asm volatile(
        "mma.sync.aligned.m16n8k16.row.col.f32.f16.f16.f32 "
        "{%0,%1,%2,%3}, {%4,%5,%6,%7}, {%8,%9}, {%0,%1,%2,%3};"
        : "+f"(d[0]), "+f"(d[1]), "+f"(d[2]), "+f"(d[3])
        : "r"(a[0]), "r"(a[1]), "r"(a[2]), "r"(a[3]), "r"(b0), "r"(b1));
}
__device__ __forceinline__ uint32_t pack2(__half a, __half b) {
    return (uint32_t)__half_as_ushort(a) | ((uint32_t)__half_as_ushort(b) << 16);
}

// ---------------------------------------------------------------------------
__global__ void conv_x_kernel(const float4* __restrict__ x4) {
    int row  = blockIdx.x * 8 + (threadIdx.x >> 5);
    int lane = threadIdx.x & 31;
    const float4* p = x4 + (size_t)row * ROW_F4;
    uint2* hi = (uint2*)(g_xh + (size_t)row * DIMV);
#pragma unroll
    for (int c = 0; c < 4; ++c) {
        float4 v = p[c * 32 + lane];
        uint2 H;
        H.x = pack2(__float2half_rn(v.x), __float2half_rn(v.y));
        H.y = pack2(__float2half_rn(v.z), __float2half_rn(v.w));
        hi[c * 32 + lane] = H;
    }
}

__global__ void conv_e_kernel(const float4* __restrict__ e4) {
    int row  = blockIdx.x * 8 + (threadIdx.x >> 5);
    int lane = threadIdx.x & 31;
    const float4* p = e4 + (size_t)row * ROW_F4;
    uint2* hi = (uint2*)(g_eh + (size_t)row * DIMV);
    float s = 0.f;
#pragma unroll
    for (int c = 0; c < 4; ++c) {
        float4 v = p[c * 32 + lane];
        s += v.x * v.x + v.y * v.y + v.z * v.z + v.w * v.w;
        uint2 H;
        H.x = pack2(__float2half_rn(v.x), __float2half_rn(v.y));
        H.y = pack2(__float2half_rn(v.z), __float2half_rn(v.w));
        hi[c * 32 + lane] = H;
    }
#pragma unroll
    for (int off = 16; off; off >>= 1) s += __shfl_down_sync(0xFFFFFFFFu, s, off);
    if (lane == 0) g_esq[row] = s;
}

// ---------------------------------------------------------------------------
// Pass 1: fp16 hi*hi GEMM, per-(row, 8-code tile) approx-score maxima.
// grid (64 ntiles, 64 mtiles), 128 threads = 4 warps (2M x 2N), warp 64x64.
// ---------------------------------------------------------------------------
__global__ __launch_bounds__(128, 2) void vq_mma() {
    extern __shared__ char smem[];
    const uint32_t sb = smem_u32(smem);
    float* esq_s = (float*)(smem + NBUF * STAGEB);

    const int tid = threadIdx.x, lane = tid & 31, wid = tid >> 5;
    const int wm = wid >> 1, wn = wid & 1;
    const int mBase = blockIdx.y * BM, nBase = blockIdx.x * BN;

    if (tid < 32) ((float4*)esq_s)[tid] = ((const float4*)(g_esq + nBase))[tid];

    // cp.async: 1024 16B chunks/stage (512 A + 512 B), 8 per thread.
    const int rr = tid >> 2, cI = tid & 3;   // rr 0..31, cI 0..3

#define ISSUE(s)                                                               \
    {                                                                          \
        const int k0_ = (s) * 32;                                              \
        const uint32_t st_ = sb + ((s) & 3) * STAGEB;                          \
        _Pragma("unroll")                                                      \
        for (int j = 0; j < 4; ++j) {                                          \
            const int r_ = j * 32 + rr;                                        \
            const uint32_t d_ = (uint32_t)r_ * 64 + ((cI ^ ((r_ >> 1) & 3)) << 4); \
            cpasync16(st_ + d_,        g_xh + (size_t)(mBase + r_) * DIMV + k0_ + cI * 8); \
            cpasync16(st_ + 8192 + d_, g_eh + (size_t)(nBase + r_) * DIMV + k0_ + cI * 8); \
        }                                                                      \
        asm volatile("cp.async.commit_group;" ::: "memory");                   \
    }

    float acc[4][8][4];
#pragma unroll
    for (int a = 0; a < 4; ++a)
#pragma unroll
        for (int b = 0; b < 8; ++b)
#pragma unroll
            for (int c = 0; c < 4; ++c) acc[a][b][c] = 0.f;

    // ldsm bases: swizzle group depends only on (lane&15).
    const int l15 = lane & 15, hi16 = lane >> 4;
    const uint32_t swz = (uint32_t)((l15 >> 1) & 3);
    uint32_t aBase[4], bBase[4];
#pragma unroll
    for (int mt = 0; mt < 4; ++mt)
        aBase[mt] = (uint32_t)(wm * 64 + mt * 16 + l15) * 64;
#pragma unroll
    for (int nt2 = 0; nt2 < 4; ++nt2)
        bBase[nt2] = 8192u + (uint32_t)(wn * 64 + nt2 * 16 + l15) * 64;

    ISSUE(0); ISSUE(1); ISSUE(2);

    for (int s = 0; s < KSTAGES; ++s) {
        if (s + 3 < KSTAGES)
            asm volatile("cp.async.wait_group 2;" ::: "memory");
        else
            asm volatile("cp.async.wait_group 0;" ::: "memory");
        __syncthreads();

        const uint32_t st = sb + (s & 3) * STAGEB;
#pragma unroll
        for (int kk = 0; kk < 2; ++kk) {
            const uint32_t coloff = (((uint32_t)(kk * 2 + hi16) ^ swz) & 3) << 4;
            uint32_t a[4][4], b[4][4];
#pragma unroll
            for (int mt = 0; mt < 4; ++mt) ldsm4(a[mt], st + aBase[mt] + coloff);
#pragma unroll
            for (int nt2 = 0; nt2 < 4; ++nt2) ldsm4(b[nt2], st + bBase[nt2] + coloff);
#pragma unroll
            for (int mt = 0; mt < 4; ++mt)
#pragma unroll
                for (int nt = 0; nt < 8; ++nt) {
                    const int nt2 = nt >> 1, od = nt & 1;
                    mma16816(acc[mt][nt], a[mt], b[nt2][od], b[nt2][2 + od]);
                }
        }
        if (s + 3 < KSTAGES) ISSUE(s + 3);
    }
#undef ISSUE

    // Epilogue: per-(row, 8-code tile) max of approx score (quad-reduced).
    const int q = lane & 3, qr = lane >> 2;
#pragma unroll
    for (int mt = 0; mt < 4; ++mt) {
#pragma unroll
        for (int h = 0; h < 2; ++h) {
            const int rowG = mBase + wm * 64 + mt * 16 + h * 8 + qr;
            float* dst = g_tileMax + (size_t)rowG * TILES8 + blockIdx.x * 16 + wn * 8;
#pragma unroll
            for (int nt = 0; nt < 8; ++nt) {
                const int col = wn * 64 + nt * 8 + q * 2;
                float s0 = 2.f * acc[mt][nt][h * 2 + 0] - esq_s[col];
                float s1 = 2.f * acc[mt][nt][h * 2 + 1] - esq_s[col + 1];
                float bv = fmaxf(s0, s1);
                bv = fmaxf(bv, __shfl_xor_sync(0xFFFFFFFFu, bv, 1));
                bv = fmaxf(bv, __shfl_xor_sync(0xFFFFFFFFu, bv, 2));
                if (q == 0) dst[nt] = bv;
            }
        }
    }
}

// ---------------------------------------------------------------------------
// Pass 2: 2 warps per row (each owns 512 tiles). Scan tile maxima, exact fp32
// rescore of candidates, argmax (ties -> smallest idx), gather + index.
// 256 threads = 8 warps = 4 rows per CTA.
// ---------------------------------------------------------------------------
__global__ __launch_bounds__(256) void rescore_kernel(
        const float4* __restrict__ x4, const float4* __restrict__ e4,
        float* __restrict__ out, int nRows) {
    __shared__ float xs[4][DIMV];
    __shared__ float sMax[4][2];
    __shared__ float sBV[4][2];
    __shared__ int   sBI[4][2];

    const int tid = threadIdx.x, lane = tid & 31, wid = tid >> 5;
    const int rl = wid >> 1, half = wid & 1;
    const int row = blockIdx.x * 4 + rl;

    // Stage x: each warp loads its half of the row (64 f4).
    float4* xs4 = (float4*)xs[rl];
#pragma unroll
    for (int c = 0; c < 2; ++c)
        xs4[half * 64 + c * 32 + lane] =
            x4[(size_t)row * ROW_F4 + half * 64 + c * 32 + lane];

    // Load this warp's 512 tile maxima (4 f4 per lane), local max.
    const float4* tm4 = (const float4*)(g_tileMax + (size_t)row * TILES8);
    float4 tv[4];
    float m = -3.4e38f;
#pragma unroll
    for (int j = 0; j < 4; ++j) {
        tv[j] = tm4[half * 128 + j * 32 + lane];
        m = fmaxf(m, fmaxf(fmaxf(tv[j].x, tv[j].y), fmaxf(tv[j].z, tv[j].w)));
    }
#pragma unroll
    for (int off = 16; off; off >>= 1)
        m = fmaxf(m, __shfl_xor_sync(0xFFFFFFFFu, m, off));
    if (lane == 0) sMax[rl][half] = m;
    __syncthreads();
    const float thr = fmaxf(sMax[rl][0], sMax[rl][1]) - EPS;

    float bv = -3.4e38f; int bi = 0x7FFFFFFF;
    const int qq = lane & 3, code8 = lane >> 2;

#pragma unroll
    for (int j = 0; j < 4; ++j) {
        bool any = (tv[j].x >= thr) | (tv[j].y >= thr) |
                   (tv[j].z >= thr) | (tv[j].w >= thr);
        unsigned mask = __ballot_sync(0xFFFFFFFFu, any);
        while (mask) {
            const int src = __ffs(mask) - 1;
            mask &= mask - 1;
            float cc[4];
            cc[0] = __shfl_sync(0xFFFFFFFFu, tv[j].x, src);
            cc[1] = __shfl_sync(0xFFFFFFFFu, tv[j].y, src);
            cc[2] = __shfl_sync(0xFFFFFFFFu, tv[j].z, src);
            cc[3] = __shfl_sync(0xFFFFFFFFu, tv[j].w, src);
#pragma unroll
            for (int comp = 0; comp < 4; ++comp) {
                if (cc[comp] < thr) continue;
                const int t = (half * 128 + j * 32 + src) * 4 + comp;
                const int code = t * 8 + code8;   // 8 codes/tile, 4 lanes/code
                const float4* ep = e4 + (size_t)code * ROW_F4;
                float d = 0.f;
#pragma unroll
                for (int c = 0; c < 32; ++c) {
                    float4 ev = ep[qq * 32 + c];
                    float4 xv = xs4[qq * 32 + c];
                    d += ev.x * xv.x + ev.y * xv.y + ev.z * xv.z + ev.w * xv.w;
                }
                d += __shfl_xor_sync(0xFFFFFFFFu, d, 1);
                d += __shfl_xor_sync(0xFFFFFFFFu, d, 2);
                if (qq == 0) {
                    float s = 2.f * d - g_esq[code];
                    if (s > bv || (s == bv && code < bi)) { bv = s; bi = code; }
                }
            }
        }
    }

#pragma unroll
    for (int off = 16; off; off >>= 1) {
        float ov = __shfl_xor_sync(0xFFFFFFFFu, bv, off);
        int   oi = __shfl_xor_sync(0xFFFFFFFFu, bi, off);
        if (ov > bv || (ov == bv && oi < bi)) { bv = ov; bi = oi; }
    }
    if (lane == 0) { sBV[rl][half] = bv; sBI[rl][half] = bi; }
    __syncthreads();

    if (half == 0) {
        float v0 = sBV[rl][0], v1 = sBV[rl][1];
        int   i0 = sBI[rl][0], i1 = sBI[rl][1];
        int idx = (v1 > v0 || (v1 == v0 && i1 < i0)) ? i1 : i0;
        const float4* src = e4 + (size_t)idx * ROW_F4;
        float4* dst = (float4*)out + (size_t)row * ROW_F4;
#pragma unroll
        for (int c = 0; c < 4; ++c) dst[lane + 32 * c] = src[lane + 32 * c];
        if (lane == 0) out[(size_t)nRows * DIMV + row] = (float)idx;
    }
}

// ---------------------------------------------------------------------------
extern "C" void kernel_launch(void* const* d_in, const int* in_sizes, int n_in,
                              void* d_out, int out_size) {
    const float4* x4 = (const float4*)d_in[0];
    const float4* e4 = (const float4*)d_in[1];
    float* out = (float*)d_out;
    const int nRows = in_sizes[0] / DIMV;   // 8192
    const int kRows = in_sizes[1] / DIMV;   // 8192

    static int smemSet = 0;
    if (!smemSet) {
        cudaFuncSetAttribute(vq_mma, cudaFuncAttributeMaxDynamicSharedMemorySize, SMEMSZ);
        smemSet = 1;
    }

    conv_x_kernel<<<nRows / 8, 256>>>(x4);
    conv_e_kernel<<<kRows / 8, 256>>>(e4);
    vq_mma<<<dim3(KCB / BN, nRows / BM), 128, SMEMSZ>>>();
    rescore_kernel<<<nRows / 4, 256>>>(x4, e4, out, nRows);
}